// round 5
// baseline (speedup 1.0000x reference)
#include <cuda_runtime.h>
#include <math.h>

// ---------------- problem constants ----------------
#define N_NODES 50000
#define N_EDGES 600000

// ---------------- scratch (no allocations allowed) ----------------
__device__ float g_B1[(size_t)N_NODES * 128];   // [N,128] buffer
__device__ float g_B2[(size_t)N_NODES * 256];   // [N,256] buffer
__device__ float g_dinv[N_NODES];
__device__ int   g_indptr[N_NODES + 1];
__device__ int   g_cursor[N_NODES];             // counts, then fill cursor
__device__ int   g_srcs[N_EDGES];
__device__ int   g_blocksums[128];

// ================= CSR build =================
__global__ void k_zero(int* cursor) {
    int i = blockIdx.x * blockDim.x + threadIdx.x;
    if (i < N_NODES) cursor[i] = 0;
}

__global__ void k_count(int* cursor, const int* __restrict__ ei) {
    int e = blockIdx.x * blockDim.x + threadIdx.x;
    if (e < N_EDGES) atomicAdd(&cursor[ei[N_EDGES + e]], 1);
}

// per-block inclusive scan of 512 counts -> exclusive indptr (local), dinv
__global__ void k_scan1(const int* __restrict__ counts, int* indptr,
                        int* blocksums, float* dinv) {
    __shared__ int sm[512];
    int i = blockIdx.x * 512 + threadIdx.x;
    int c = (i < N_NODES) ? counts[i] : 0;
    if (i < N_NODES) dinv[i] = rsqrtf((float)(c + 1));  // +1 self loop
    sm[threadIdx.x] = c;
    __syncthreads();
#pragma unroll
    for (int off = 1; off < 512; off <<= 1) {
        int v = (threadIdx.x >= off) ? sm[threadIdx.x - off] : 0;
        __syncthreads();
        sm[threadIdx.x] += v;
        __syncthreads();
    }
    if (i < N_NODES) indptr[i] = sm[threadIdx.x] - c;  // exclusive
    if (threadIdx.x == 511) blocksums[blockIdx.x] = sm[511];
}

__global__ void k_scan2(int* blocksums, int nb) {
    __shared__ int sm[128];
    int t = threadIdx.x;
    int v = (t < nb) ? blocksums[t] : 0;
    sm[t] = v;
    __syncthreads();
#pragma unroll
    for (int off = 1; off < 128; off <<= 1) {
        int u = (t >= off) ? sm[t - off] : 0;
        __syncthreads();
        sm[t] += u;
        __syncthreads();
    }
    if (t < nb) blocksums[t] = sm[t] - v;  // exclusive block offsets
}

__global__ void k_scan3(int* indptr, const int* __restrict__ blocksums, int* cursor) {
    int i = blockIdx.x * blockDim.x + threadIdx.x;
    if (i < N_NODES) {
        indptr[i] += blocksums[i >> 9];
        cursor[i] = 0;
    }
    if (i == 0) indptr[N_NODES] = N_EDGES;
}

__global__ void k_fill(const int* __restrict__ ei, const int* __restrict__ indptr,
                       int* cursor, int* srcs) {
    int e = blockIdx.x * blockDim.x + threadIdx.x;
    if (e >= N_EDGES) return;
    int d = ei[N_EDGES + e];
    int pos = indptr[d] + atomicAdd(&cursor[d], 1);
    srcs[pos] = ei[e];
}

// ================= gather aggregation, 128 channels =================
// one warp per dst node; unroll-4 with dual accumulators for MLP
__global__ void k_gather128(const float* __restrict__ H, float* __restrict__ OUT,
                            const int* __restrict__ indptr, const int* __restrict__ srcs,
                            const float* __restrict__ dinv,
                            const float* __restrict__ bias, int do_relu) {
    int gt = blockIdx.x * blockDim.x + threadIdx.x;
    int n = gt >> 5;
    int lane = gt & 31;
    if (n >= N_NODES) return;
    const float4* Hv = (const float4*)H;
    float dn = dinv[n];
    float s0 = dn * dn;
    float4 accA = Hv[n * 32 + lane];
    accA.x *= s0; accA.y *= s0; accA.z *= s0; accA.w *= s0;
    float4 accB = make_float4(0.f, 0.f, 0.f, 0.f);
    int j = indptr[n], end = indptr[n + 1];
    for (; j + 3 < end; j += 4) {
        int s1 = srcs[j], s2 = srcs[j + 1], s3 = srcs[j + 2], s4 = srcs[j + 3];
        float n1 = dinv[s1] * dn, n2 = dinv[s2] * dn;
        float n3 = dinv[s3] * dn, n4 = dinv[s4] * dn;
        float4 v1 = Hv[s1 * 32 + lane];
        float4 v2 = Hv[s2 * 32 + lane];
        float4 v3 = Hv[s3 * 32 + lane];
        float4 v4 = Hv[s4 * 32 + lane];
        accA.x += v1.x * n1 + v3.x * n3;
        accA.y += v1.y * n1 + v3.y * n3;
        accA.z += v1.z * n1 + v3.z * n3;
        accA.w += v1.w * n1 + v3.w * n3;
        accB.x += v2.x * n2 + v4.x * n4;
        accB.y += v2.y * n2 + v4.y * n4;
        accB.z += v2.z * n2 + v4.z * n4;
        accB.w += v2.w * n2 + v4.w * n4;
    }
    for (; j < end; j++) {
        int s1 = srcs[j];
        float n1 = dinv[s1] * dn;
        float4 v1 = Hv[s1 * 32 + lane];
        accA.x += v1.x * n1; accA.y += v1.y * n1;
        accA.z += v1.z * n1; accA.w += v1.w * n1;
    }
    accA.x += accB.x; accA.y += accB.y; accA.z += accB.z; accA.w += accB.w;
    if (bias) {
        float4 b = ((const float4*)bias)[lane];
        accA.x += b.x; accA.y += b.y; accA.z += b.z; accA.w += b.w;
    }
    if (do_relu) {
        accA.x = fmaxf(accA.x, 0.f); accA.y = fmaxf(accA.y, 0.f);
        accA.z = fmaxf(accA.z, 0.f); accA.w = fmaxf(accA.w, 0.f);
    }
    ((float4*)OUT)[n * 32 + lane] = accA;
}

// ================= SGEMM with packed f32x2 FMA =================
// C[M,N] = A[M,K] @ B[K,N] (+bias, relu). BM=BN=128, BK=8, 256 threads,
// 8x8/thread. B pre-duplicated in smem as (b,b) ull pairs; double-buffered.
typedef unsigned long long ull;

__device__ __forceinline__ ull pack2(float lo, float hi) {
    ull r;
    asm("mov.b64 %0, {%1, %2};" : "=l"(r) : "r"(__float_as_uint(lo)), "r"(__float_as_uint(hi)));
    return r;
}
__device__ __forceinline__ void unpack2(ull v, float& lo, float& hi) {
    unsigned a, b;
    asm("mov.b64 {%0, %1}, %2;" : "=r"(a), "=r"(b) : "l"(v));
    lo = __uint_as_float(a); hi = __uint_as_float(b);
}
__device__ __forceinline__ void fma2(ull& d, ull a, ull b) {
    asm("fma.rn.f32x2 %0, %1, %2, %0;" : "+l"(d) : "l"(a), "l"(b));
}

__global__ __launch_bounds__(256) void k_sgemm2(const float* __restrict__ A,
                                                const float* __restrict__ B,
                                                float* __restrict__ C,
                                                int M, int K, int N,
                                                const float* __restrict__ bias,
                                                int do_relu) {
    __shared__ __align__(16) float As[2][8][128];   // [buf][k][row]
    __shared__ __align__(16) ull   Bsd[2][8][128];  // [buf][k][col] duplicated pairs

    int tid = threadIdx.x;
    int tx = tid & 15;         // 0..15 col octs
    int ty = tid >> 4;         // 0..15 row octs
    int rowBase = blockIdx.y * 128;
    int colBase = blockIdx.x * 128;

    int arow = tid >> 1;            // 0..127
    int ak   = (tid & 1) * 4;       // 0 or 4
    int brow = tid >> 5;            // 0..7
    int bcol = (tid & 31) * 4;      // 0..124

    ull acc[4][8];                  // [row-pair][col] packed (r2i, r2i+1)
#pragma unroll
    for (int i = 0; i < 4; i++)
#pragma unroll
        for (int j = 0; j < 8; j++) acc[i][j] = 0ull;

    // prologue: load tile 0
    {
        int gr = rowBase + arow;
        float4 av = make_float4(0.f, 0.f, 0.f, 0.f);
        if (gr < M) av = *(const float4*)(A + (size_t)gr * K + ak);
        As[0][ak + 0][arow] = av.x;
        As[0][ak + 1][arow] = av.y;
        As[0][ak + 2][arow] = av.z;
        As[0][ak + 3][arow] = av.w;
        float4 bv = *(const float4*)(B + (size_t)brow * N + colBase + bcol);
        Bsd[0][brow][bcol + 0] = pack2(bv.x, bv.x);
        Bsd[0][brow][bcol + 1] = pack2(bv.y, bv.y);
        Bsd[0][brow][bcol + 2] = pack2(bv.z, bv.z);
        Bsd[0][brow][bcol + 3] = pack2(bv.w, bv.w);
    }
    __syncthreads();

    int buf = 0;
    for (int k0 = 0; k0 < K; k0 += 8) {
        // prefetch next tile into registers
        float4 av_n, bv_n;
        bool has_next = (k0 + 8 < K);
        if (has_next) {
            int gr = rowBase + arow;
            av_n = make_float4(0.f, 0.f, 0.f, 0.f);
            if (gr < M) av_n = *(const float4*)(A + (size_t)gr * K + k0 + 8 + ak);
            bv_n = *(const float4*)(B + (size_t)(k0 + 8 + brow) * N + colBase + bcol);
        }

#pragma unroll
        for (int kk = 0; kk < 8; kk++) {
            ulonglong2 a01 = *(const ulonglong2*)&As[buf][kk][ty * 8];      // rows 0,1 / 2,3
            ulonglong2 a23 = *(const ulonglong2*)&As[buf][kk][ty * 8 + 4];  // rows 4,5 / 6,7
            ulonglong2 b0 = *(const ulonglong2*)&Bsd[buf][kk][tx * 8];
            ulonglong2 b1 = *(const ulonglong2*)&Bsd[buf][kk][tx * 8 + 2];
            ulonglong2 b2 = *(const ulonglong2*)&Bsd[buf][kk][tx * 8 + 4];
            ulonglong2 b3 = *(const ulonglong2*)&Bsd[buf][kk][tx * 8 + 6];
            ull ap[4] = {a01.x, a01.y, a23.x, a23.y};
            ull bd[8] = {b0.x, b0.y, b1.x, b1.y, b2.x, b2.y, b3.x, b3.y};
#pragma unroll
            for (int i = 0; i < 4; i++)
#pragma unroll
                for (int j = 0; j < 8; j++) fma2(acc[i][j], ap[i], bd[j]);
        }

        if (has_next) {
            int nb = buf ^ 1;
            As[nb][ak + 0][arow] = av_n.x;
            As[nb][ak + 1][arow] = av_n.y;
            As[nb][ak + 2][arow] = av_n.z;
            As[nb][ak + 3][arow] = av_n.w;
            Bsd[nb][brow][bcol + 0] = pack2(bv_n.x, bv_n.x);
            Bsd[nb][brow][bcol + 1] = pack2(bv_n.y, bv_n.y);
            Bsd[nb][brow][bcol + 2] = pack2(bv_n.z, bv_n.z);
            Bsd[nb][brow][bcol + 3] = pack2(bv_n.w, bv_n.w);
            __syncthreads();
            buf = nb;
        }
    }

    // epilogue
#pragma unroll
    for (int i = 0; i < 4; i++) {
        float lo[8], hi[8];
#pragma unroll
        for (int j = 0; j < 8; j++) unpack2(acc[i][j], lo[j], hi[j]);
#pragma unroll
        for (int p = 0; p < 2; p++) {
            int row = rowBase + ty * 8 + 2 * i + p;
            if (row >= M) continue;
            float* src = p ? hi : lo;
            float o[8];
#pragma unroll
            for (int j = 0; j < 8; j++) {
                float v = src[j];
                if (bias) v += bias[colBase + tx * 8 + j];
                if (do_relu) v = fmaxf(v, 0.f);
                o[j] = v;
            }
            float* outp = C + (size_t)row * N + colBase + tx * 8;
            *(float4*)(outp) = make_float4(o[0], o[1], o[2], o[3]);
            *(float4*)(outp + 4) = make_float4(o[4], o[5], o[6], o[7]);
        }
    }
}

// ================= layer 3 =================
__global__ void k_gemm_small(const float* __restrict__ H2, const float* __restrict__ W3,
                             float* __restrict__ H3) {
    __shared__ float w[256];
    if (threadIdx.x < 256) w[threadIdx.x] = W3[threadIdx.x];
    __syncthreads();
    int r = blockIdx.x * blockDim.x + threadIdx.x;
    if (r >= N_NODES) return;
    float a0 = 0.f, a1 = 0.f;
    const float4* row = (const float4*)(H2 + (size_t)r * 128);
#pragma unroll
    for (int k = 0; k < 32; k++) {
        float4 v = row[k];
        int b = k * 8;
        a0 += v.x * w[b + 0] + v.y * w[b + 2] + v.z * w[b + 4] + v.w * w[b + 6];
        a1 += v.x * w[b + 1] + v.y * w[b + 3] + v.z * w[b + 5] + v.w * w[b + 7];
    }
    H3[(size_t)r * 2 + 0] = a0;
    H3[(size_t)r * 2 + 1] = a1;
}

// gather 2ch + bias + log_softmax, one thread per node
__global__ void k_gather2_lsm(const float* __restrict__ H3, float* __restrict__ OUT,
                              const int* __restrict__ indptr, const int* __restrict__ srcs,
                              const float* __restrict__ dinv, const float* __restrict__ b3) {
    int n = blockIdx.x * blockDim.x + threadIdx.x;
    if (n >= N_NODES) return;
    float dn = dinv[n];
    float s0 = dn * dn;
    float2 h = *(const float2*)(H3 + (size_t)n * 2);
    float a0 = h.x * s0, a1 = h.y * s0;
    int end = indptr[n + 1];
    for (int j = indptr[n]; j < end; j++) {
        int s = srcs[j];
        float nrm = dinv[s] * dn;
        float2 v = *(const float2*)(H3 + (size_t)s * 2);
        a0 += v.x * nrm;
        a1 += v.y * nrm;
    }
    float v0 = a0 + b3[0];
    float v1 = a1 + b3[1];
    float m = fmaxf(v0, v1);
    float lse = m + logf(expf(v0 - m) + expf(v1 - m));
    OUT[(size_t)n * 2 + 0] = v0 - lse;
    OUT[(size_t)n * 2 + 1] = v1 - lse;
}

// ---------------- launch ----------------
extern "C" void kernel_launch(void* const* d_in, const int* in_sizes, int n_in,
                              void* d_out, int out_size) {
    const float* x  = (const float*)d_in[0];
    const float* W1 = (const float*)d_in[1];
    const float* b1 = (const float*)d_in[2];
    const float* W2 = (const float*)d_in[3];
    const float* b2 = (const float*)d_in[4];
    const float* W3 = (const float*)d_in[5];
    const float* b3 = (const float*)d_in[6];
    const int*   ei = (const int*)d_in[7];   // int32 (JAX x64 disabled)
    float* out = (float*)d_out;

    float *B1, *B2, *dinv;
    int *indptr, *cursor, *srcs, *blocksums;
    cudaGetSymbolAddress((void**)&B1, g_B1);
    cudaGetSymbolAddress((void**)&B2, g_B2);
    cudaGetSymbolAddress((void**)&dinv, g_dinv);
    cudaGetSymbolAddress((void**)&indptr, g_indptr);
    cudaGetSymbolAddress((void**)&cursor, g_cursor);
    cudaGetSymbolAddress((void**)&srcs, g_srcs);
    cudaGetSymbolAddress((void**)&blocksums, g_blocksums);

    const int N = N_NODES, E = N_EDGES, TB = 256;
    const int nScanBlocks = (N + 511) / 512;  // 98

    // ---- CSR build + dinv ----
    k_zero <<<(N + TB - 1) / TB, TB>>>(cursor);
    k_count<<<(E + TB - 1) / TB, TB>>>(cursor, ei);
    k_scan1<<<nScanBlocks, 512>>>(cursor, indptr, blocksums, dinv);
    k_scan2<<<1, 128>>>(blocksums, nScanBlocks);
    k_scan3<<<(N + TB - 1) / TB, TB>>>(indptr, blocksums, cursor);
    k_fill <<<(E + TB - 1) / TB, TB>>>(ei, indptr, cursor, srcs);

    // ---- layer 1: agg(x) -> B1; relu((A x)@W1 + b1) -> B2 ----
    k_gather128<<<(N * 32 + TB - 1) / TB, TB>>>(x, B1, indptr, srcs, dinv, nullptr, 0);
    {
        dim3 g(2, (N + 127) / 128);
        k_sgemm2<<<g, 256>>>(B1, W1, B2, N, 128, 256, b1, 1);
    }

    // ---- layer 2: h1@W2 -> B1; relu(agg + b2) -> B2 ----
    {
        dim3 g(1, (N + 127) / 128);
        k_sgemm2<<<g, 256>>>(B2, W2, B1, N, 256, 128, nullptr, 0);
    }
    k_gather128<<<(N * 32 + TB - 1) / TB, TB>>>(B1, B2, indptr, srcs, dinv, b2, 1);

    // ---- layer 3: h2@W3 -> B1[:, :2]; agg + b3 + log_softmax -> out ----
    k_gemm_small<<<(N + TB - 1) / TB, TB>>>(B2, W3, B1);
    k_gather2_lsm<<<(N + TB - 1) / TB, TB>>>(B1, out, indptr, srcs, dinv, b3);
}

// round 6
// speedup vs baseline: 1.9181x; 1.9181x over previous
#include <cuda_runtime.h>
#include <math.h>

// ---------------- problem constants ----------------
#define N_NODES 50000
#define N_EDGES 600000

// ---------------- scratch (no allocations allowed) ----------------
__device__ float g_B1[(size_t)N_NODES * 128];   // [N,128] buffer
__device__ float g_B2[(size_t)N_NODES * 256];   // [N,256] buffer
__device__ float g_dinv[N_NODES];
__device__ int   g_indptr[N_NODES + 1];
__device__ int   g_cursor[N_NODES];             // counts, then fill cursor
__device__ int   g_srcs[N_EDGES];
__device__ int   g_blocksums[128];

// ================= CSR build =================
__global__ void k_zero(int* cursor) {
    int i = blockIdx.x * blockDim.x + threadIdx.x;
    if (i < N_NODES) cursor[i] = 0;
}

__global__ void k_count(int* cursor, const int* __restrict__ ei) {
    int e = blockIdx.x * blockDim.x + threadIdx.x;
    if (e < N_EDGES) atomicAdd(&cursor[ei[N_EDGES + e]], 1);
}

// per-block inclusive scan of 512 counts -> exclusive indptr (local), dinv
__global__ void k_scan1(const int* __restrict__ counts, int* indptr,
                        int* blocksums, float* dinv) {
    __shared__ int sm[512];
    int i = blockIdx.x * 512 + threadIdx.x;
    int c = (i < N_NODES) ? counts[i] : 0;
    if (i < N_NODES) dinv[i] = rsqrtf((float)(c + 1));  // +1 self loop
    sm[threadIdx.x] = c;
    __syncthreads();
#pragma unroll
    for (int off = 1; off < 512; off <<= 1) {
        int v = (threadIdx.x >= off) ? sm[threadIdx.x - off] : 0;
        __syncthreads();
        sm[threadIdx.x] += v;
        __syncthreads();
    }
    if (i < N_NODES) indptr[i] = sm[threadIdx.x] - c;  // exclusive
    if (threadIdx.x == 511) blocksums[blockIdx.x] = sm[511];
}

__global__ void k_scan2(int* blocksums, int nb) {
    __shared__ int sm[128];
    int t = threadIdx.x;
    int v = (t < nb) ? blocksums[t] : 0;
    sm[t] = v;
    __syncthreads();
#pragma unroll
    for (int off = 1; off < 128; off <<= 1) {
        int u = (t >= off) ? sm[t - off] : 0;
        __syncthreads();
        sm[t] += u;
        __syncthreads();
    }
    if (t < nb) blocksums[t] = sm[t] - v;  // exclusive block offsets
}

__global__ void k_scan3(int* indptr, const int* __restrict__ blocksums, int* cursor) {
    int i = blockIdx.x * blockDim.x + threadIdx.x;
    if (i < N_NODES) {
        indptr[i] += blocksums[i >> 9];
        cursor[i] = 0;
    }
    if (i == 0) indptr[N_NODES] = N_EDGES;
}

__global__ void k_fill(const int* __restrict__ ei, const int* __restrict__ indptr,
                       int* cursor, int* srcs) {
    int e = blockIdx.x * blockDim.x + threadIdx.x;
    if (e >= N_EDGES) return;
    int d = ei[N_EDGES + e];
    int pos = indptr[d] + atomicAdd(&cursor[d], 1);
    srcs[pos] = ei[e];
}

// ================= gather aggregation, 128 channels =================
// one warp per dst node; unroll-4 with dual accumulators for MLP
__global__ void k_gather128(const float* __restrict__ H, float* __restrict__ OUT,
                            const int* __restrict__ indptr, const int* __restrict__ srcs,
                            const float* __restrict__ dinv,
                            const float* __restrict__ bias, int do_relu) {
    int gt = blockIdx.x * blockDim.x + threadIdx.x;
    int n = gt >> 5;
    int lane = gt & 31;
    if (n >= N_NODES) return;
    const float4* Hv = (const float4*)H;
    float dn = dinv[n];
    float s0 = dn * dn;
    float4 accA = Hv[n * 32 + lane];
    accA.x *= s0; accA.y *= s0; accA.z *= s0; accA.w *= s0;
    float4 accB = make_float4(0.f, 0.f, 0.f, 0.f);
    int j = indptr[n], end = indptr[n + 1];
    for (; j + 3 < end; j += 4) {
        int s1 = srcs[j], s2 = srcs[j + 1], s3 = srcs[j + 2], s4 = srcs[j + 3];
        float n1 = dinv[s1] * dn, n2 = dinv[s2] * dn;
        float n3 = dinv[s3] * dn, n4 = dinv[s4] * dn;
        float4 v1 = Hv[s1 * 32 + lane];
        float4 v2 = Hv[s2 * 32 + lane];
        float4 v3 = Hv[s3 * 32 + lane];
        float4 v4 = Hv[s4 * 32 + lane];
        accA.x += v1.x * n1 + v3.x * n3;
        accA.y += v1.y * n1 + v3.y * n3;
        accA.z += v1.z * n1 + v3.z * n3;
        accA.w += v1.w * n1 + v3.w * n3;
        accB.x += v2.x * n2 + v4.x * n4;
        accB.y += v2.y * n2 + v4.y * n4;
        accB.z += v2.z * n2 + v4.z * n4;
        accB.w += v2.w * n2 + v4.w * n4;
    }
    for (; j < end; j++) {
        int s1 = srcs[j];
        float n1 = dinv[s1] * dn;
        float4 v1 = Hv[s1 * 32 + lane];
        accA.x += v1.x * n1; accA.y += v1.y * n1;
        accA.z += v1.z * n1; accA.w += v1.w * n1;
    }
    accA.x += accB.x; accA.y += accB.y; accA.z += accB.z; accA.w += accB.w;
    if (bias) {
        float4 b = ((const float4*)bias)[lane];
        accA.x += b.x; accA.y += b.y; accA.z += b.z; accA.w += b.w;
    }
    if (do_relu) {
        accA.x = fmaxf(accA.x, 0.f); accA.y = fmaxf(accA.y, 0.f);
        accA.z = fmaxf(accA.z, 0.f); accA.w = fmaxf(accA.w, 0.f);
    }
    ((float4*)OUT)[n * 32 + lane] = accA;
}

// ================= SGEMM with packed f32x2 FMA (R4 known-good) =================
// C[M,N] = A[M,K] @ B[K,N] (+bias, relu). BM=BN=128, BK=8, 256 threads, 8x8/thread.
typedef unsigned long long ull;

__device__ __forceinline__ ull pack2(float lo, float hi) {
    ull r;
    asm("mov.b64 %0, {%1, %2};" : "=l"(r) : "r"(__float_as_uint(lo)), "r"(__float_as_uint(hi)));
    return r;
}
__device__ __forceinline__ void unpack2(ull v, float& lo, float& hi) {
    unsigned a, b;
    asm("mov.b64 {%0, %1}, %2;" : "=r"(a), "=r"(b) : "l"(v));
    lo = __uint_as_float(a); hi = __uint_as_float(b);
}
__device__ __forceinline__ void fma2(ull& d, ull a, ull b) {
    asm("fma.rn.f32x2 %0, %1, %2, %0;" : "+l"(d) : "l"(a), "l"(b));
}

__global__ __launch_bounds__(256) void k_sgemm2(const float* __restrict__ A,
                                                const float* __restrict__ B,
                                                float* __restrict__ C,
                                                int M, int K, int N,
                                                const float* __restrict__ bias,
                                                int do_relu) {
    __shared__ __align__(16) float As[8][128];  // [k][row]
    __shared__ __align__(16) float Bs[8][128];  // [k][col]

    int tid = threadIdx.x;
    int tx = tid & 15;         // 0..15 col octs
    int ty = tid >> 4;         // 0..15 row octs
    int rowBase = blockIdx.y * 128;
    int colBase = blockIdx.x * 128;

    int arow = tid >> 1;            // 0..127
    int ak   = (tid & 1) * 4;       // 0 or 4
    int brow = tid >> 5;            // 0..7
    int bcol = (tid & 31) * 4;      // 0..124

    ull acc[4][8];                  // [row-pair][col] packed (r2i, r2i+1)
#pragma unroll
    for (int i = 0; i < 4; i++)
#pragma unroll
        for (int j = 0; j < 8; j++) acc[i][j] = 0ull;

    for (int k0 = 0; k0 < K; k0 += 8) {
        int gr = rowBase + arow;
        float4 av = make_float4(0.f, 0.f, 0.f, 0.f);
        if (gr < M) av = *(const float4*)(A + (size_t)gr * K + k0 + ak);
        As[ak + 0][arow] = av.x;
        As[ak + 1][arow] = av.y;
        As[ak + 2][arow] = av.z;
        As[ak + 3][arow] = av.w;

        float4 bv = *(const float4*)(B + (size_t)(k0 + brow) * N + colBase + bcol);
        *(float4*)&Bs[brow][bcol] = bv;
        __syncthreads();

#pragma unroll
        for (int kk = 0; kk < 8; kk++) {
            ulonglong2 a01 = *(const ulonglong2*)&As[kk][ty * 8];       // rows (0,1),(2,3)
            ulonglong2 a23 = *(const ulonglong2*)&As[kk][ty * 8 + 4];   // rows (4,5),(6,7)
            float4 b0 = *(const float4*)&Bs[kk][tx * 8];
            float4 b1 = *(const float4*)&Bs[kk][tx * 8 + 4];
            ull ap[4] = {a01.x, a01.y, a23.x, a23.y};
            ull bd[8];
            bd[0] = pack2(b0.x, b0.x); bd[1] = pack2(b0.y, b0.y);
            bd[2] = pack2(b0.z, b0.z); bd[3] = pack2(b0.w, b0.w);
            bd[4] = pack2(b1.x, b1.x); bd[5] = pack2(b1.y, b1.y);
            bd[6] = pack2(b1.z, b1.z); bd[7] = pack2(b1.w, b1.w);
#pragma unroll
            for (int i = 0; i < 4; i++)
#pragma unroll
                for (int j = 0; j < 8; j++) fma2(acc[i][j], ap[i], bd[j]);
        }
        __syncthreads();
    }

    // epilogue
#pragma unroll
    for (int i = 0; i < 4; i++) {
        float lo[8], hi[8];
#pragma unroll
        for (int j = 0; j < 8; j++) unpack2(acc[i][j], lo[j], hi[j]);
#pragma unroll
        for (int p = 0; p < 2; p++) {
            int row = rowBase + ty * 8 + 2 * i + p;
            if (row >= M) continue;
            float* src = p ? hi : lo;
            float o[8];
#pragma unroll
            for (int j = 0; j < 8; j++) {
                float v = src[j];
                if (bias) v += bias[colBase + tx * 8 + j];
                if (do_relu) v = fmaxf(v, 0.f);
                o[j] = v;
            }
            float* outp = C + (size_t)row * N + colBase + tx * 8;
            *(float4*)(outp) = make_float4(o[0], o[1], o[2], o[3]);
            *(float4*)(outp + 4) = make_float4(o[4], o[5], o[6], o[7]);
        }
    }
}

// ================= layer 3 =================
__global__ void k_gemm_small(const float* __restrict__ H2, const float* __restrict__ W3,
                             float* __restrict__ H3) {
    __shared__ float w[256];
    if (threadIdx.x < 256) w[threadIdx.x] = W3[threadIdx.x];
    __syncthreads();
    int r = blockIdx.x * blockDim.x + threadIdx.x;
    if (r >= N_NODES) return;
    float a0 = 0.f, a1 = 0.f;
    const float4* row = (const float4*)(H2 + (size_t)r * 128);
#pragma unroll
    for (int k = 0; k < 32; k++) {
        float4 v = row[k];
        int b = k * 8;
        a0 += v.x * w[b + 0] + v.y * w[b + 2] + v.z * w[b + 4] + v.w * w[b + 6];
        a1 += v.x * w[b + 1] + v.y * w[b + 3] + v.z * w[b + 5] + v.w * w[b + 7];
    }
    H3[(size_t)r * 2 + 0] = a0;
    H3[(size_t)r * 2 + 1] = a1;
}

// gather 2ch + bias + log_softmax, one thread per node
__global__ void k_gather2_lsm(const float* __restrict__ H3, float* __restrict__ OUT,
                              const int* __restrict__ indptr, const int* __restrict__ srcs,
                              const float* __restrict__ dinv, const float* __restrict__ b3) {
    int n = blockIdx.x * blockDim.x + threadIdx.x;
    if (n >= N_NODES) return;
    float dn = dinv[n];
    float s0 = dn * dn;
    float2 h = *(const float2*)(H3 + (size_t)n * 2);
    float a0 = h.x * s0, a1 = h.y * s0;
    int end = indptr[n + 1];
    for (int j = indptr[n]; j < end; j++) {
        int s = srcs[j];
        float nrm = dinv[s] * dn;
        float2 v = *(const float2*)(H3 + (size_t)s * 2);
        a0 += v.x * nrm;
        a1 += v.y * nrm;
    }
    float v0 = a0 + b3[0];
    float v1 = a1 + b3[1];
    float m = fmaxf(v0, v1);
    float lse = m + logf(expf(v0 - m) + expf(v1 - m));
    OUT[(size_t)n * 2 + 0] = v0 - lse;
    OUT[(size_t)n * 2 + 1] = v1 - lse;
}

// ---------------- launch ----------------
extern "C" void kernel_launch(void* const* d_in, const int* in_sizes, int n_in,
                              void* d_out, int out_size) {
    const float* x  = (const float*)d_in[0];
    const float* W1 = (const float*)d_in[1];
    const float* b1 = (const float*)d_in[2];
    const float* W2 = (const float*)d_in[3];
    const float* b2 = (const float*)d_in[4];
    const float* W3 = (const float*)d_in[5];
    const float* b3 = (const float*)d_in[6];
    const int*   ei = (const int*)d_in[7];   // int32 (JAX x64 disabled)
    float* out = (float*)d_out;

    float *B1, *B2, *dinv;
    int *indptr, *cursor, *srcs, *blocksums;
    cudaGetSymbolAddress((void**)&B1, g_B1);
    cudaGetSymbolAddress((void**)&B2, g_B2);
    cudaGetSymbolAddress((void**)&dinv, g_dinv);
    cudaGetSymbolAddress((void**)&indptr, g_indptr);
    cudaGetSymbolAddress((void**)&cursor, g_cursor);
    cudaGetSymbolAddress((void**)&srcs, g_srcs);
    cudaGetSymbolAddress((void**)&blocksums, g_blocksums);

    const int N = N_NODES, E = N_EDGES, TB = 256;
    const int nScanBlocks = (N + 511) / 512;  // 98

    // ---- CSR build + dinv ----
    k_zero <<<(N + TB - 1) / TB, TB>>>(cursor);
    k_count<<<(E + TB - 1) / TB, TB>>>(cursor, ei);
    k_scan1<<<nScanBlocks, 512>>>(cursor, indptr, blocksums, dinv);
    k_scan2<<<1, 128>>>(blocksums, nScanBlocks);
    k_scan3<<<(N + TB - 1) / TB, TB>>>(indptr, blocksums, cursor);
    k_fill <<<(E + TB - 1) / TB, TB>>>(ei, indptr, cursor, srcs);

    // ---- layer 1: agg(x) -> B1; relu((A x)@W1 + b1) -> B2 ----
    k_gather128<<<(N * 32 + TB - 1) / TB, TB>>>(x, B1, indptr, srcs, dinv, nullptr, 0);
    {
        dim3 g(2, (N + 127) / 128);
        k_sgemm2<<<g, 256>>>(B1, W1, B2, N, 128, 256, b1, 1);
    }

    // ---- layer 2: h1@W2 -> B1; relu(agg + b2) -> B2 ----
    {
        dim3 g(1, (N + 127) / 128);
        k_sgemm2<<<g, 256>>>(B2, W2, B1, N, 256, 128, nullptr, 0);
    }
    k_gather128<<<(N * 32 + TB - 1) / TB, TB>>>(B1, B2, indptr, srcs, dinv, b2, 1);

    // ---- layer 3: h2@W3 -> B1[:, :2]; agg + b3 + log_softmax -> out ----
    k_gemm_small<<<(N + TB - 1) / TB, TB>>>(B2, W3, B1);
    k_gather2_lsm<<<(N + TB - 1) / TB, TB>>>(B1, out, indptr, srcs, dinv, b3);
}